// round 13
// baseline (speedup 1.0000x reference)
#include <cuda_runtime.h>
#include <cuda_bf16.h>

#define PADDING_IDX 0
#define SMOOTHING   0.1f
#define MAX_ROWS    8192

// Generation-tagged partial slots: {f32 value, u32 gen} in one aligned 8B word.
// One 8B store publishes value+tag atomically -> no fences/atomics anywhere.
// __device__ globals: allocation-free per harness rules.
__device__ unsigned long long g_slot[MAX_ROWS];   // zero-init: gen=0
__device__ unsigned int       g_gen = 0;          // bumped by spinner each launch

__device__ __forceinline__ void slot_store(int r, float v, unsigned int gen) {
    unsigned long long w =
        ((unsigned long long)gen << 32) | (unsigned long long)__float_as_uint(v);
    asm volatile("st.global.volatile.u64 [%0], %1;"
                 :: "l"(&g_slot[r]), "l"(w) : "memory");
}
__device__ __forceinline__ unsigned long long slot_load(int r) {
    unsigned long long w;
    asm volatile("ld.global.volatile.u64 %0, [%1];"
                 : "=l"(w) : "l"(&g_slot[r]) : "memory");
    return w;
}

// grid = N+1. blockIdx 1..N: one row each, unroll-2 dual-accumulator stream
// (two independent LDG.128 chains/iter -> deeper MLP, half the FADD-chain
// pressure; measured ~0.9us faster in R5). blockIdx 0: hot consume-as-ready
// sweep spinner (best measured tail, R10).
// NOTE: target is int32 on device (JAX x64-disabled downcasts int64 -> int32).
__global__ void __launch_bounds__(256)
ls_kernel(const float* __restrict__ x,
          const int* __restrict__ target,
          float* __restrict__ out,
          int V, int N)
{
    __shared__ float sh[8];
    const unsigned int gen = g_gen + 1u;   // L2-hot broadcast; stable during launch

    if (blockIdx.x != 0) {
        // ---------------- worker: stream one row ----------------
        const int r = blockIdx.x - 1;
        const int t = target[r];

        if (t == PADDING_IDX || t < 0 || t >= V) {
            if (threadIdx.x == 0) slot_store(r, 0.0f, gen);
            return;
        }

        const size_t row_off = (size_t)r * (size_t)V;
        const float4* __restrict__ row4 = reinterpret_cast<const float4*>(x + row_off);
        const int nv4 = V >> 2;                      // 32000 -> 8000 float4

        // Unroll-2, two accumulators: 2 independent 16B loads in flight per
        // iter, accumulator chains decoupled from each other.
        float s0 = 0.0f, s1 = 0.0f;
        int i = threadIdx.x;
        for (; i + 256 < nv4; i += 512) {
            float4 a = row4[i];
            float4 b = row4[i + 256];
            s0 += (a.x + a.y) + (a.z + a.w);
            s1 += (b.x + b.y) + (b.z + b.w);
        }
        for (; i < nv4; i += 256) {
            float4 a = row4[i];
            s0 += (a.x + a.y) + (a.z + a.w);
        }
        float s = s0 + s1;
        for (int j = (nv4 << 2) + threadIdx.x; j < V; j += 256)
            s += x[row_off + j];                     // tail (unused for V=32000)

        #pragma unroll
        for (int o = 16; o > 0; o >>= 1)
            s += __shfl_down_sync(0xffffffffu, s, o);
        if ((threadIdx.x & 31) == 0) sh[threadIdx.x >> 5] = s;
        __syncthreads();

        if (threadIdx.x < 32) {
            float v = (threadIdx.x < 8) ? sh[threadIdx.x] : 0.0f;
            #pragma unroll
            for (int o = 4; o > 0; o >>= 1)
                v += __shfl_down_sync(0xffffffffu, v, o);
            if (threadIdx.x == 0) {
                const float g = x[row_off + (size_t)t];   // gather, L2-hot
                slot_store(r, -(SMOOTHING / (float)V) * v - (1.0f - SMOOTHING) * g, gen);
            }
        }
        return;
    }

    // ------------- spinner (block 0): hot consume-as-ready sweep -------------
    // Thread t owns slots {t, t+256, ..., t+3840}; fixed slot order per thread
    // -> deterministic accumulation.
    const int nslots = (N + 255) >> 8;               // 16 for N=4096
    float acc[16];
    #pragma unroll
    for (int k = 0; k < 16; k++) acc[k] = 0.0f;

    unsigned int pend = (nslots >= 32) ? 0xFFFFFFFFu : ((1u << nslots) - 1u);
    #pragma unroll
    for (int k = 0; k < 16; k++)
        if ((int)threadIdx.x + (k << 8) >= N) pend &= ~(1u << k);

    while (pend) {
        unsigned int made = 0;
        #pragma unroll
        for (int k = 0; k < 16; k++) {
            if (pend & (1u << k)) {
                unsigned long long w = slot_load(threadIdx.x + (k << 8));
                if ((unsigned int)(w >> 32) == gen) {
                    acc[k] = __uint_as_float((unsigned int)w);
                    pend &= ~(1u << k);
                    made = 1;
                }
            }
        }
        if (!made) __nanosleep(128);                 // back off only when stalled
    }

    float s = 0.0f;
    #pragma unroll
    for (int k = 0; k < 16; k++) s += acc[k];

    #pragma unroll
    for (int o = 16; o > 0; o >>= 1)
        s += __shfl_down_sync(0xffffffffu, s, o);
    if ((threadIdx.x & 31) == 0) sh[threadIdx.x >> 5] = s;
    __syncthreads();

    if (threadIdx.x < 32) {
        float v = (threadIdx.x < 8) ? sh[threadIdx.x] : 0.0f;
        #pragma unroll
        for (int o = 4; o > 0; o >>= 1)
            v += __shfl_down_sync(0xffffffffu, v, o);
        if (threadIdx.x == 0) {
            out[0] = v;
            g_gen = gen;   // next replay expects gen+1 (kernel-boundary visibility)
        }
    }
}

extern "C" void kernel_launch(void* const* d_in, const int* in_sizes, int n_in,
                              void* d_out, int out_size)
{
    const float* x      = (const float*)d_in[0];
    const int*   target = (const int*)d_in[1];
    float*       out    = (float*)d_out;

    const int N = in_sizes[1];         // 4096 rows
    const int V = in_sizes[0] / N;     // 32000 vocab

    ls_kernel<<<N + 1, 256>>>(x, target, out, V, N);
}

// round 14
// speedup vs baseline: 1.0062x; 1.0062x over previous
#include <cuda_runtime.h>
#include <cuda_bf16.h>

#define PADDING_IDX 0
#define SMOOTHING   0.1f
#define MAX_ROWS    8192

// Generation-tagged partial slots: {f32 value, u32 gen} in one aligned 8B word.
// One 8B store publishes value+tag atomically -> no fences/atomics anywhere.
// __device__ globals: allocation-free per harness rules.
__device__ unsigned long long g_slot[MAX_ROWS];   // zero-init: gen=0
__device__ unsigned int       g_gen = 0;          // bumped by spinner each launch

__device__ __forceinline__ void slot_store(int r, float v, unsigned int gen) {
    unsigned long long w =
        ((unsigned long long)gen << 32) | (unsigned long long)__float_as_uint(v);
    asm volatile("st.global.volatile.u64 [%0], %1;"
                 :: "l"(&g_slot[r]), "l"(w) : "memory");
}
__device__ __forceinline__ unsigned long long slot_load(int r) {
    unsigned long long w;
    asm volatile("ld.global.volatile.u64 %0, [%1];"
                 : "=l"(w) : "l"(&g_slot[r]) : "memory");
    return w;
}

// grid = N+1. blockIdx 1..N: one row each, unroll-2 dual-accumulator stream.
// __launch_bounds__(256, 8) FORCES 32 regs -> 8 blocks/SM (R13 hit 40 regs,
// dropped to 6 blocks/SM, occ 68% -> regression; occupancy is the binding
// constraint for this streamer). blockIdx 0: hot consume-as-ready sweep
// spinner (best measured tail, R10).
// NOTE: target is int32 on device (JAX x64-disabled downcasts int64 -> int32).
__global__ void __launch_bounds__(256, 8)
ls_kernel(const float* __restrict__ x,
          const int* __restrict__ target,
          float* __restrict__ out,
          int V, int N)
{
    __shared__ float sh[8];
    const unsigned int gen = g_gen + 1u;   // L2-hot broadcast; stable during launch

    if (blockIdx.x != 0) {
        // ---------------- worker: stream one row ----------------
        const int r = blockIdx.x - 1;
        const int t = target[r];

        if (t == PADDING_IDX || t < 0 || t >= V) {
            if (threadIdx.x == 0) slot_store(r, 0.0f, gen);
            return;
        }

        const size_t row_off = (size_t)r * (size_t)V;
        const float4* __restrict__ row4 = reinterpret_cast<const float4*>(x + row_off);
        const int nv4 = V >> 2;                      // 32000 -> 8000 float4

        // Unroll-2, two accumulators: 2 independent 16B loads in flight per
        // iter; reg budget capped at 32 by launch bounds.
        float s0 = 0.0f, s1 = 0.0f;
        int i = threadIdx.x;
        for (; i + 256 < nv4; i += 512) {
            float4 a = row4[i];
            float4 b = row4[i + 256];
            s0 += (a.x + a.y) + (a.z + a.w);
            s1 += (b.x + b.y) + (b.z + b.w);
        }
        for (; i < nv4; i += 256) {
            float4 a = row4[i];
            s0 += (a.x + a.y) + (a.z + a.w);
        }
        float s = s0 + s1;
        for (int j = (nv4 << 2) + threadIdx.x; j < V; j += 256)
            s += x[row_off + j];                     // tail (unused for V=32000)

        #pragma unroll
        for (int o = 16; o > 0; o >>= 1)
            s += __shfl_down_sync(0xffffffffu, s, o);
        if ((threadIdx.x & 31) == 0) sh[threadIdx.x >> 5] = s;
        __syncthreads();

        if (threadIdx.x < 32) {
            float v = (threadIdx.x < 8) ? sh[threadIdx.x] : 0.0f;
            #pragma unroll
            for (int o = 4; o > 0; o >>= 1)
                v += __shfl_down_sync(0xffffffffu, v, o);
            if (threadIdx.x == 0) {
                const float g = x[row_off + (size_t)t];   // gather, L2-hot
                slot_store(r, -(SMOOTHING / (float)V) * v - (1.0f - SMOOTHING) * g, gen);
            }
        }
        return;
    }

    // ------------- spinner (block 0): hot consume-as-ready sweep -------------
    // Thread t owns slots {t, t+256, ..., t+3840}; fixed slot order per thread
    // -> deterministic accumulation.
    const int nslots = (N + 255) >> 8;               // 16 for N=4096
    float acc[16];
    #pragma unroll
    for (int k = 0; k < 16; k++) acc[k] = 0.0f;

    unsigned int pend = (nslots >= 32) ? 0xFFFFFFFFu : ((1u << nslots) - 1u);
    #pragma unroll
    for (int k = 0; k < 16; k++)
        if ((int)threadIdx.x + (k << 8) >= N) pend &= ~(1u << k);

    while (pend) {
        unsigned int made = 0;
        #pragma unroll
        for (int k = 0; k < 16; k++) {
            if (pend & (1u << k)) {
                unsigned long long w = slot_load(threadIdx.x + (k << 8));
                if ((unsigned int)(w >> 32) == gen) {
                    acc[k] = __uint_as_float((unsigned int)w);
                    pend &= ~(1u << k);
                    made = 1;
                }
            }
        }
        if (!made) __nanosleep(128);                 // back off only when stalled
    }

    float s = 0.0f;
    #pragma unroll
    for (int k = 0; k < 16; k++) s += acc[k];

    #pragma unroll
    for (int o = 16; o > 0; o >>= 1)
        s += __shfl_down_sync(0xffffffffu, s, o);
    if ((threadIdx.x & 31) == 0) sh[threadIdx.x >> 5] = s;
    __syncthreads();

    if (threadIdx.x < 32) {
        float v = (threadIdx.x < 8) ? sh[threadIdx.x] : 0.0f;
        #pragma unroll
        for (int o = 4; o > 0; o >>= 1)
            v += __shfl_down_sync(0xffffffffu, v, o);
        if (threadIdx.x == 0) {
            out[0] = v;
            g_gen = gen;   // next replay expects gen+1 (kernel-boundary visibility)
        }
    }
}

extern "C" void kernel_launch(void* const* d_in, const int* in_sizes, int n_in,
                              void* d_out, int out_size)
{
    const float* x      = (const float*)d_in[0];
    const int*   target = (const int*)d_in[1];
    float*       out    = (float*)d_out;

    const int N = in_sizes[1];         // 4096 rows
    const int V = in_sizes[0] / N;     // 32000 vocab

    ls_kernel<<<N + 1, 256>>>(x, target, out, V, N);
}

// round 15
// speedup vs baseline: 1.0303x; 1.0239x over previous
#include <cuda_runtime.h>
#include <cuda_bf16.h>

#define PADDING_IDX 0
#define SMOOTHING   0.1f
#define MAX_ROWS    8192

// Generation-tagged partial slots: {f32 value, u32 gen} in one aligned 8B word.
// One 8B store publishes value+tag atomically -> no fences/atomics anywhere.
// __device__ globals: allocation-free per harness rules.
__device__ unsigned long long g_slot[MAX_ROWS];   // zero-init: gen=0
__device__ unsigned int       g_gen = 0;          // bumped by spinner each launch

__device__ __forceinline__ void slot_store(int r, float v, unsigned int gen) {
    unsigned long long w =
        ((unsigned long long)gen << 32) | (unsigned long long)__float_as_uint(v);
    asm volatile("st.global.volatile.u64 [%0], %1;"
                 :: "l"(&g_slot[r]), "l"(w) : "memory");
}
__device__ __forceinline__ unsigned long long slot_load(int r) {
    unsigned long long w;
    asm volatile("ld.global.volatile.u64 %0, [%1];"
                 : "=l"(w) : "l"(&g_slot[r]) : "memory");
    return w;
}

// grid = N+1. blockIdx 1..N: one row each (simple single-accumulator float4
// stream: 32 regs -> 8 blocks/SM, the measured optimum). blockIdx 0: hot
// consume-as-ready sweep spinner — consumes partials as they arrive, so the
// tail after the last worker is ~1 sweep instead of a 4.5us dependent kernel.
// Per-thread accumulation order is fixed (slot index order) -> deterministic.
// NOTE: target is int32 on device (JAX x64-disabled downcasts int64 -> int32).
__global__ void __launch_bounds__(256)
ls_kernel(const float* __restrict__ x,
          const int* __restrict__ target,
          float* __restrict__ out,
          int V, int N)
{
    __shared__ float sh[8];
    const unsigned int gen = g_gen + 1u;   // L2-hot broadcast; stable during launch

    if (blockIdx.x != 0) {
        // ---------------- worker: stream one row ----------------
        const int r = blockIdx.x - 1;
        const int t = target[r];

        if (t == PADDING_IDX || t < 0 || t >= V) {
            if (threadIdx.x == 0) slot_store(r, 0.0f, gen);
            return;
        }

        const size_t row_off = (size_t)r * (size_t)V;
        const float4* __restrict__ row4 = reinterpret_cast<const float4*>(x + row_off);
        const int nv4 = V >> 2;                      // 32000 -> 8000 float4

        float s = 0.0f;
        for (int i = threadIdx.x; i < nv4; i += blockDim.x) {
            float4 v = row4[i];
            s += (v.x + v.y) + (v.z + v.w);
        }
        for (int i = (nv4 << 2) + threadIdx.x; i < V; i += blockDim.x)
            s += x[row_off + i];                     // tail (unused for V=32000)

        #pragma unroll
        for (int o = 16; o > 0; o >>= 1)
            s += __shfl_down_sync(0xffffffffu, s, o);
        if ((threadIdx.x & 31) == 0) sh[threadIdx.x >> 5] = s;
        __syncthreads();

        if (threadIdx.x < 32) {
            float v = (threadIdx.x < 8) ? sh[threadIdx.x] : 0.0f;
            #pragma unroll
            for (int o = 4; o > 0; o >>= 1)
                v += __shfl_down_sync(0xffffffffu, v, o);
            if (threadIdx.x == 0) {
                const float g = x[row_off + (size_t)t];   // gather, L2-hot
                slot_store(r, -(SMOOTHING / (float)V) * v - (1.0f - SMOOTHING) * g, gen);
            }
        }
        return;
    }

    // ------------- spinner (block 0): consume-as-ready sweep -------------
    // Thread t owns slots {t, t+256, ..., t+3840}. Accumulation is in fixed
    // slot order per thread via ordered bit-scan of `pend` -> deterministic.
    const int nslots = (N + 255) >> 8;               // 16 for N=4096
    float acc[16];
    #pragma unroll
    for (int k = 0; k < 16; k++) acc[k] = 0.0f;

    unsigned int pend = (nslots >= 32) ? 0xFFFFFFFFu : ((1u << nslots) - 1u);
    // mask off slots beyond N
    #pragma unroll
    for (int k = 0; k < 16; k++)
        if ((int)threadIdx.x + (k << 8) >= N) pend &= ~(1u << k);

    while (pend) {
        unsigned int made = 0;
        #pragma unroll
        for (int k = 0; k < 16; k++) {
            if (pend & (1u << k)) {
                // independent volatile loads across k -> pipelined (MLP)
                unsigned long long w = slot_load(threadIdx.x + (k << 8));
                if ((unsigned int)(w >> 32) == gen) {
                    acc[k] = __uint_as_float((unsigned int)w);
                    pend &= ~(1u << k);
                    made = 1;
                }
            }
        }
        if (!made) __nanosleep(128);                 // back off only if stalled
    }

    // fixed-order per-thread sum, then block reduce
    float s = 0.0f;
    #pragma unroll
    for (int k = 0; k < 16; k++) s += acc[k];

    #pragma unroll
    for (int o = 16; o > 0; o >>= 1)
        s += __shfl_down_sync(0xffffffffu, s, o);
    if ((threadIdx.x & 31) == 0) sh[threadIdx.x >> 5] = s;
    __syncthreads();

    if (threadIdx.x < 32) {
        float v = (threadIdx.x < 8) ? sh[threadIdx.x] : 0.0f;
        #pragma unroll
        for (int o = 4; o > 0; o >>= 1)
            v += __shfl_down_sync(0xffffffffu, v, o);
        if (threadIdx.x == 0) {
            out[0] = v;
            g_gen = gen;   // next replay expects gen+1 (kernel-boundary visibility)
        }
    }
}

extern "C" void kernel_launch(void* const* d_in, const int* in_sizes, int n_in,
                              void* d_out, int out_size)
{
    const float* x      = (const float*)d_in[0];
    const int*   target = (const int*)d_in[1];
    float*       out    = (float*)d_out;

    const int N = in_sizes[1];         // 4096 rows
    const int V = in_sizes[0] / N;     // 32000 vocab

    ls_kernel<<<N + 1, 256>>>(x, target, out, V, N);
}